// round 10
// baseline (speedup 1.0000x reference)
#include <cuda_runtime.h>

// APMLSparse: x[B,N,3], y[B,M,3] fp32 -> scalar loss. B=4, N=M=4096.
// Per row: d_j = sqrt(max(||x-y_j||^2,1e-12)), e_j=exp(-d_j), Z=sum e_j.
// Kept = d-ascending prefix while exclusive cumulative mass < 0.8*Z (incl.
// crossing entry, p>1e-10 filter). loss += sum_kept e_j*d_j / Z.
//
// R8 (= R4 404us baseline + surgical cuts):
//  - 16 bins of width 0.5 over [0,8) (crossing bin ~28% of elems, was 55%)
//  - stage-2 sub-bins width 1/32 -> final band ~70 elems
//  - stage-2 / compact paths on float compares (no F2I off the hot path)
//  - compact appends via direct atomicAdd (band tiny; ballot machinery gone)
//  Private banked histogram hist[bin*512+tid] (conflict-free, zero atomics),
//  read-and-clear bin reduces, d register-resident, per-thread rcpZ row fold.

#define NTH  512
#define NPT  8              // 4096 / NTH
#define RPC  8
#define MPTS 4096
#define NB   16
#define CAP2 512
#define HIST_BYTES (NB * NTH * 4)   // 32 KB

__global__ void apml_zero_out(float* o) { o[0] = 0.0f; }

__global__ __launch_bounds__(NTH, 2)
void apml_kernel(const float* __restrict__ x, const float* __restrict__ y,
                 float* __restrict__ out)
{
    extern __shared__ float hist[];     // NB*NTH floats (32 KB dynamic)
    __shared__ float l2d[CAP2];         // final band (~70 elems typical)
    __shared__ float l2e[CAP2];
    __shared__ float binTot[NB];
    __shared__ float warpRed[16];
    __shared__ float s_ctl[8];  // 0:T 1:c1lo 2:c1hi 3:mLo1 4:rcpZ 5:c1bits 6:eThr
    __shared__ float s_ctl2[4]; // 0:lA 1:hA 2:mLo2
    __shared__ int   s_cnt;

    const int tid = threadIdx.x, lane = tid & 31, wid = tid >> 5;
    const int cpb = MPTS / RPC;                    // 512
    const int b = blockIdx.x / cpb;
    const int rowBase = (blockIdx.x % cpb) * RPC;

    // 8 y-points per thread in registers, reused across RPC rows.
    float yx[NPT], yy[NPT], yz[NPT];
    const float* yb = y + (size_t)b * MPTS * 3;
#pragma unroll
    for (int k = 0; k < NPT; k++) {
        int j = k * NTH + tid;
        yx[k] = yb[j * 3 + 0];
        yy[k] = yb[j * 3 + 1];
        yz[k] = yb[j * 3 + 2];
    }

    // Initial histogram zero (read-and-clear reduces keep it clean after).
    float4* h4 = (float4*)hist;
#pragma unroll
    for (int i = 0; i < NB * NTH / 4 / NTH; i++)
        h4[tid + i * NTH] = make_float4(0.f, 0.f, 0.f, 0.f);

    float ctaAcc = 0.0f;
    __syncthreads();

    for (int r = 0; r < RPC; r++) {
        const float* xp = x + ((size_t)b * MPTS + rowBase + r) * 3;
        const float x0 = __ldg(xp + 0);
        const float x1 = __ldg(xp + 1);
        const float x2 = __ldg(xp + 2);

        // ---- pass 1: distances -> regs, exp-mass -> 16 bins of width 0.5 ----
        float dreg[NPT];
#pragma unroll
        for (int k = 0; k < NPT; k++) {
            float dx = x0 - yx[k];
            float dy = x1 - yy[k];
            float dz = x2 - yz[k];
            float sq = fmaf(dx, dx, fmaf(dy, dy, dz * dz));
            sq = fmaxf(sq, 1e-12f);
            float d = sq * rsqrtf(sq);               // sqrt via MUFU.RSQ + FMUL
            dreg[k] = d;
            float ex = __expf(-d);
            int bin = (int)(2.0f * d);
            bin = bin < (NB - 1) ? bin : (NB - 1);   // clamp d>=7.5 tail
            hist[bin * NTH + tid] += ex;             // conflict-free column
        }
        __syncthreads();

        // ---- reduce stage-1 bins and zero them: warp w -> bin w ----
        {
            float4* col = (float4*)(hist + wid * NTH);
            float s = 0.f;
#pragma unroll
            for (int i = 0; i < NTH / 4 / 32; i++) {
                float4 v = col[lane + 32 * i];
                s += (v.x + v.y) + (v.z + v.w);
                col[lane + 32 * i] = make_float4(0.f, 0.f, 0.f, 0.f);
            }
#pragma unroll
            for (int o = 16; o; o >>= 1) s += __shfl_xor_sync(0xffffffffu, s, o);
            if (lane == 0) binTot[wid] = s;
        }
        __syncthreads();

        // ---- scan stage 1 (warp 0; 16 live lanes) ----
        if (wid == 0) {
            float mm = (lane < NB) ? binTot[lane] : 0.f;
            float incl = mm;
#pragma unroll
            for (int o = 1; o < 32; o <<= 1) {
                float t = __shfl_up_sync(0xffffffffu, incl, o);
                if (lane >= o) incl += t;
            }
            float total = __shfl_sync(0xffffffffu, incl, 31);
            float T = 0.8f * total;
            float excl = incl - mm;
            unsigned bal = __ballot_sync(0xffffffffu,
                                         (lane < NB) && (excl < T) && (incl >= T));
            int c1 = bal ? (__ffs(bal) - 1) : (NB - 1);
            float mlo = __shfl_sync(0xffffffffu, excl, c1);
            if (lane == 0) {
                s_ctl[0] = T;
                s_ctl[1] = 0.5f * (float)c1;                       // bin low edge
                s_ctl[2] = (c1 >= NB - 1) ? 1e30f : 0.5f * (float)(c1 + 1);
                s_ctl[3] = mlo;
                s_ctl[4] = __frcp_rn(total);
                s_ctl[5] = __int_as_float(c1);
                s_ctl[6] = 1e-10f * total;                         // eThr
                s_cnt = 0;   // safe: >=2 barriers since prior-row last use
            }
        }
        __syncthreads();
        const float T    = s_ctl[0];
        const float c1lo = s_ctl[1];
        const float c1hi = s_ctl[2];
        const float mLo1 = s_ctl[3];
        const float rcpZ = s_ctl[4];
        const int   c1i  = __float_as_int(s_ctl[5]);
        const float eThr = s_ctl[6];

        // ---- stage-2: below-bin kept FMA; in-bin -> 16 sub-bins (width 1/32) ----
        float acc = 0.0f;
#pragma unroll
        for (int k = 0; k < NPT; k++) {
            float d = dreg[k];
            if (d < c1lo) {
                acc = fmaf(__expf(-d), d, acc);
            } else if (d < c1hi) {
                int sb = (int)(32.0f * d) - (c1i << 4);  // exact: 2^ scalings
                sb = sb < (NB - 1) ? sb : (NB - 1);      // c1i==15 tail clamp
                hist[sb * NTH + tid] += __expf(-d);
            }
        }
        __syncthreads();

        // ---- reduce sub-bins and zero them ----
        {
            float4* col = (float4*)(hist + wid * NTH);
            float s = 0.f;
#pragma unroll
            for (int i = 0; i < NTH / 4 / 32; i++) {
                float4 v = col[lane + 32 * i];
                s += (v.x + v.y) + (v.z + v.w);
                col[lane + 32 * i] = make_float4(0.f, 0.f, 0.f, 0.f);
            }
#pragma unroll
            for (int o = 16; o; o >>= 1) s += __shfl_xor_sync(0xffffffffu, s, o);
            if (lane == 0) binTot[wid] = s;
        }
        __syncthreads();

        // ---- scan sub-bins ----
        if (wid == 0) {
            float mm = (lane < NB) ? binTot[lane] : 0.f;
            float incl = mm;
#pragma unroll
            for (int o = 1; o < 32; o <<= 1) {
                float t = __shfl_up_sync(0xffffffffu, incl, o);
                if (lane >= o) incl += t;
            }
            float excl = incl - mm;
            unsigned bal = __ballot_sync(0xffffffffu,
                (lane < NB) && (mLo1 + excl < T) && (mLo1 + incl >= T));
            int ce = bal ? (__ffs(bal) - 1) : (NB - 1);   // fp-mismatch fallback
            float mlo2 = mLo1 + __shfl_sync(0xffffffffu, excl, ce);
            if (lane == 0) {
                int sb32 = (c1i << 4) + ce;               // global 1/32 sub-bin id
                s_ctl2[0] = (float)sb32 * 0.03125f;       // exact fp
                s_ctl2[1] = (c1i == NB - 1 && ce == NB - 1)
                              ? 1e30f : (float)(sb32 + 1) * 0.03125f;
                s_ctl2[2] = mlo2;
            }
        }
        __syncthreads();
        const float lA   = s_ctl2[0];
        const float hA   = s_ctl2[1];
        const float mLo2 = s_ctl2[2];

        // ---- compact: kept sub-bins [c1lo,lA) FMA; band [lA,hA) -> list ----
#pragma unroll
        for (int k = 0; k < NPT; k++) {
            float d = dreg[k];
            if (d < lA) {
                if (d >= c1lo)                        // below-c1lo already added
                    acc = fmaf(__expf(-d), d, acc);
            } else if (d < hA) {
                int idx = atomicAdd(&s_cnt, 1);       // band is tiny (~70)
                float ex = __expf(-d);
                if (idx < CAP2) { l2d[idx] = d; l2e[idx] = ex; }
                else            acc = fmaf(ex, d, acc);   // overflow fallback
            }
        }
        __syncthreads();

        // ---- exact O(k^2) rank resolution on the ~70-element band ----
        const int   cnt  = s_cnt < CAP2 ? s_cnt : CAP2;
        const float Trem = T - mLo2;
        for (int i = tid; i < cnt; i += NTH) {
            float di = l2d[i], ei = l2e[i], rm = 0.f;
            for (int j = 0; j < cnt; j++) {
                float dj = l2d[j];
                rm += ((dj < di) || (dj == di && j < i)) ? l2e[j] : 0.f;
            }
            if (rm < Trem && ei > eThr) acc = fmaf(ei, di, acc);
        }

        // ---- fold row into per-thread accumulator ----
        ctaAcc = fmaf(acc, rcpZ, ctaAcc);
        // next row's pass-1/reduce-1 barriers precede the s_cnt reset and any
        // l2d overwrite, so prior-row reads stay ordered.
    }

    // ---- one block reduce per CTA ----
#pragma unroll
    for (int o = 16; o; o >>= 1) ctaAcc += __shfl_xor_sync(0xffffffffu, ctaAcc, o);
    if (lane == 0) warpRed[wid] = ctaAcc;
    __syncthreads();
    if (tid == 0) {
        float tot = 0.f;
#pragma unroll
        for (int i = 0; i < 16; i++) tot += warpRed[i];
        atomicAdd(out, tot);
    }
}

extern "C" void kernel_launch(void* const* d_in, const int* in_sizes, int n_in,
                              void* d_out, int out_size)
{
    const float* x = (const float*)d_in[0];
    const float* y = (const float*)d_in[1];
    float* out = (float*)d_out;

    cudaFuncSetAttribute(apml_kernel,
                         cudaFuncAttributeMaxDynamicSharedMemorySize, HIST_BYTES);

    apml_zero_out<<<1, 1>>>(out);
    const int grid = (4 * MPTS) / RPC;   // 2048 CTAs
    apml_kernel<<<grid, NTH, HIST_BYTES>>>(x, y, out);
}

// round 13
// speedup vs baseline: 1.9727x; 1.9727x over previous
#include <cuda_runtime.h>

// APMLSparse: x[B,N,3], y[B,M,3] fp32 -> scalar loss. B=4, N=M=4096.
// Per row: d_j = sqrt(max(||x-y_j||^2,1e-12)), e_j=exp(-d_j), Z=sum e_j.
// Kept = d-ascending prefix while exclusive cumulative mass < 0.8*Z (incl.
// crossing entry, p>1e-10 filter). loss += sum_kept e_j*d_j / Z.
//
// R9 = exact R4 structure (404us best: width-1 16-bin private banked
// histogram, stage-2 sub-bins width 1/16, in-bin-guarded ballot compact,
// penta round, recompact, exact O(k^2)) with ONLY two uniform-code deletions
// validated by R5: (a) histogram zeroing fused into read-and-clear reduces,
// (b) per-row block reduce replaced by per-thread rcpZ fold. No control-flow
// reshaping (cause of the R6-R8 regressions).

#define NTH   512
#define NPT   8            // 4096 / NTH
#define RPC   8
#define MPTS  4096
#define NB    16           // bins per stage
#define HISTN (NB * NTH)   // 8192 floats = 32 KB
#define CAP   512
#define CAP2  128

__global__ void apml_zero_out(float* o) { o[0] = 0.0f; }

__global__ __launch_bounds__(NTH, 2)
void apml_kernel(const float* __restrict__ x, const float* __restrict__ y,
                 float* __restrict__ out)
{
    __shared__ float  hist[HISTN];      // 32 KB private histogram columns
    __shared__ float2 list[CAP];        // 4 KB crossing-window elements
    __shared__ float  l2d[CAP2];        // final band
    __shared__ float  l2e[CAP2];
    __shared__ float  binTot[NB];
    __shared__ float  warpRed[64];
    __shared__ float  s_ctl[10];  // 0:Z 1:T 2:(c1|l2f) 3:h2f 4:mLo 5:l3 6:h3 7:mLo3 8:rcpZ
    __shared__ int    s_int[2];

    const int tid  = threadIdx.x, lane = tid & 31, wid = tid >> 5;
    const int cpb  = MPTS / RPC;                    // 512
    const int b    = blockIdx.x / cpb;
    const int rowBase = (blockIdx.x % cpb) * RPC;

    // 8 y-points per thread in registers, reused across RPC rows.
    float yx[NPT], yy[NPT], yz[NPT];
    const float* yb = y + (size_t)b * MPTS * 3;
#pragma unroll
    for (int k = 0; k < NPT; k++) {
        int j = k * NTH + tid;
        yx[k] = yb[j * 3 + 0];
        yy[k] = yb[j * 3 + 1];
        yz[k] = yb[j * 3 + 2];
    }

    // Initial histogram zero; read-and-clear reduces keep it clean afterwards.
    float4* hist4 = (float4*)hist;
#pragma unroll
    for (int i = 0; i < HISTN / 4 / NTH; i++)
        hist4[tid + i * NTH] = make_float4(0.f, 0.f, 0.f, 0.f);

    float ctaAcc = 0.0f;
    __syncthreads();

    for (int r = 0; r < RPC; r++) {
        const float* xp = x + ((size_t)b * MPTS + rowBase + r) * 3;
        const float x0 = __ldg(xp + 0);
        const float x1 = __ldg(xp + 1);
        const float x2 = __ldg(xp + 2);

        // ---- pass 1 fused with stage-1 fill: bins of width 1 over [0,16) ----
        float dreg[NPT];
#pragma unroll
        for (int k = 0; k < NPT; k++) {
            float dx = x0 - yx[k];
            float dy = x1 - yy[k];
            float dz = x2 - yz[k];
            float sq = fmaf(dx, dx, fmaf(dy, dy, dz * dz));
            sq = fmaxf(sq, 1e-12f);
            float d = sq * rsqrtf(sq);              // sqrt via MUFU.RSQ + FMUL
            dreg[k] = d;
            float e = __expf(-d);
            int bin = (int)d;
            bin = bin < (NB - 1) ? bin : (NB - 1);  // clamp stray large d
            hist[bin * NTH + tid] += e;             // conflict-free column
        }
        __syncthreads();

        // ---- stage-1 reduce: warp w sums bin w via float4 (and clears it) ----
        {
            float s = 0.f;
            int base = wid * (NTH / 4);
#pragma unroll
            for (int i = 0; i < NTH / 4 / 32; i++) {
                float4 v = hist4[base + lane + i * 32];
                s += (v.x + v.y) + (v.z + v.w);
                hist4[base + lane + i * 32] = make_float4(0.f, 0.f, 0.f, 0.f);
            }
#pragma unroll
            for (int o = 16; o; o >>= 1) s += __shfl_xor_sync(0xffffffffu, s, o);
            if (lane == 0) binTot[wid] = s;
        }
        __syncthreads();

        // ---- stage-1 scan + pick (warp 0): Z, T, crossing bin c1, mLo1 ----
        if (wid == 0) {
            float mm = (lane < NB) ? binTot[lane] : 0.f;
            float incl = mm;
#pragma unroll
            for (int o = 1; o < NB; o <<= 1) {
                float t = __shfl_up_sync(0xffffffffu, incl, o);
                if (lane >= o) incl += t;
            }
            float total = __shfl_sync(0xffffffffu, incl, NB - 1);
            float T = 0.8f * total;
            float excl = incl - mm;
            bool cross = (lane < NB) && (excl < T) && (incl >= T);
            unsigned bal = __ballot_sync(0xffffffffu, cross);
            int c1 = bal ? (__ffs(bal) - 1) : (NB - 1);
            float mlo = __shfl_sync(0xffffffffu, excl, c1);
            if (lane == 0) {
                s_ctl[0] = total;            // Z
                s_ctl[1] = T;
                s_ctl[2] = (float)c1;
                s_ctl[4] = mlo;              // mLo1
                s_ctl[8] = __frcp_rn(total); // rcpZ
                s_int[0] = 0;   // safe: >=2 barriers since prior-row readers
                s_int[1] = 0;   // copied these counts into registers
            }
        }
        __syncthreads();
        const float Z    = s_ctl[0];
        const float T    = s_ctl[1];
        const int   c1s  = ((int)s_ctl[2]) << 4;    // c1*16
        const float mLo1 = s_ctl[4];
        const float rcpZ = s_ctl[8];

        // ---- stage-2 fill: 16 sub-bins of width 1/16 over crossing bin;
        //      below-bin elements accumulate immediately (sole below-bin add) ----
        float acc = 0.0f;
#pragma unroll
        for (int k = 0; k < NPT; k++) {
            float d = dreg[k];
            int b2 = (int)(d * 16.0f) - c1s;        // exact: x16 is 2^4 scale
            if (b2 < 0) {
                acc = fmaf(__expf(-d), d, acc);
            } else if (b2 < NB) {
                hist[b2 * NTH + tid] += __expf(-d);
            }
        }
        __syncthreads();

        // ---- stage-2 reduce (and clear) ----
        {
            float s = 0.f;
            int base = wid * (NTH / 4);
#pragma unroll
            for (int i = 0; i < NTH / 4 / 32; i++) {
                float4 v = hist4[base + lane + i * 32];
                s += (v.x + v.y) + (v.z + v.w);
                hist4[base + lane + i * 32] = make_float4(0.f, 0.f, 0.f, 0.f);
            }
#pragma unroll
            for (int o = 16; o; o >>= 1) s += __shfl_xor_sync(0xffffffffu, s, o);
            if (lane == 0) binTot[wid] = s;
        }
        __syncthreads();

        // ---- stage-2 scan + pick ----
        if (wid == 0) {
            float mm = (lane < NB) ? binTot[lane] : 0.f;
            float incl = mm;
#pragma unroll
            for (int o = 1; o < NB; o <<= 1) {
                float t = __shfl_up_sync(0xffffffffu, incl, o);
                if (lane >= o) incl += t;
            }
            float excl = incl - mm;
            bool cross = (lane < NB) && (mLo1 + excl < T) && (mLo1 + incl >= T);
            unsigned bal = __ballot_sync(0xffffffffu, cross);
            int c2 = bal ? (__ffs(bal) - 1) : (NB - 1);   // fp-mismatch fallback
            float mlo2 = mLo1 + __shfl_sync(0xffffffffu, excl, c2);
            if (lane == 0) {
                float l2f = (float)(c1s + c2) * 0.0625f;  // exact fp
                s_ctl[2] = l2f;
                s_ctl[3] = l2f + 0.0625f;
                s_ctl[4] = mlo2;
            }
        }
        __syncthreads();
        const float l2f  = s_ctl[2];
        const float h2f  = s_ctl[3];
        const float mLo2 = s_ctl[4];
        const float lc   = (float)c1s * 0.0625f;    // crossing-bin low edge

        // ---- compact: in-bin kept (below l2f) FMA; band [l2f,h2f) -> list ----
#pragma unroll
        for (int k = 0; k < NPT; k++) {
            float d = dreg[k];
            bool inbin = (d >= lc) && (d < h2f);
            bool kept  = inbin && (d < l2f);
            bool band  = inbin && !kept;
            if (kept) acc = fmaf(__expf(-d), d, acc);
            unsigned mk = __ballot_sync(0xffffffffu, band);
            if (mk) {
                int leader = __ffs(mk) - 1;
                int base2 = 0;
                if (lane == leader) base2 = atomicAdd(&s_int[0], __popc(mk));
                base2 = __shfl_sync(0xffffffffu, base2, leader);
                if (band) {
                    int idx = base2 + __popc(mk & ((1u << lane) - 1u));
                    float e = __expf(-d);
                    if (idx < CAP) list[idx] = make_float2(d, e);
                    else           acc = fmaf(e, d, acc);  // overflow fallback
                }
            }
        }
        __syncthreads();
        const int cnt = s_int[0] < CAP ? s_int[0] : CAP;

        // ---- one penta round on the ~140-element list ----
        {
            float w  = (h2f - l2f) * 0.2f;
            float u1 = l2f + w, u2 = l2f + 2.f * w, u3 = l2f + 3.f * w, u4 = l2f + 4.f * w;
            float p0 = 0.f, p1 = 0.f, p2 = 0.f, p3 = 0.f;
            for (int i = tid; i < cnt; i += NTH) {
                float2 v = list[i];
                p0 += (v.x < u1) ? v.y : 0.f;
                p1 += (v.x < u2) ? v.y : 0.f;
                p2 += (v.x < u3) ? v.y : 0.f;
                p3 += (v.x < u4) ? v.y : 0.f;
            }
#pragma unroll
            for (int o = 16; o; o >>= 1) {
                p0 += __shfl_xor_sync(0xffffffffu, p0, o);
                p1 += __shfl_xor_sync(0xffffffffu, p1, o);
                p2 += __shfl_xor_sync(0xffffffffu, p2, o);
                p3 += __shfl_xor_sync(0xffffffffu, p3, o);
            }
            if (lane == 0) {
                warpRed[wid] = p0; warpRed[16 + wid] = p1;
                warpRed[32 + wid] = p2; warpRed[48 + wid] = p3;
            }
            __syncthreads();
            if (wid == 0) {
                float s = 0.f;
                if (lane < 4) {
#pragma unroll
                    for (int i = 0; i < 16; i++) s += warpRed[lane * 16 + i];
                }
                float m1 = __shfl_sync(0xffffffffu, s, 0);
                float m2 = __shfl_sync(0xffffffffu, s, 1);
                float m3 = __shfl_sync(0xffffffffu, s, 2);
                float m4 = __shfl_sync(0xffffffffu, s, 3);
                if (lane == 0) {
                    float l = l2f, h = u1, ml = mLo2;
                    if (mLo2 + m1 < T) { l = u1; h = u2; ml = mLo2 + m1;
                      if (mLo2 + m2 < T) { l = u2; h = u3; ml = mLo2 + m2;
                        if (mLo2 + m3 < T) { l = u3; h = u4; ml = mLo2 + m3;
                          if (mLo2 + m4 < T) { l = u4; h = h2f; ml = mLo2 + m4; } } } }
                    s_ctl[5] = l; s_ctl[6] = h; s_ctl[7] = ml;
                }
            }
            __syncthreads();
        }
        const float l3 = s_ctl[5], h3 = s_ctl[6], mLo3 = s_ctl[7];

        // ---- recompact final band ----
        for (int i = tid; i < cnt; i += NTH) {
            float2 v = list[i];
            if (v.x < l3) {
                acc = fmaf(v.y, v.x, acc);
            } else if (v.x < h3) {
                int idx = atomicAdd(&s_int[1], 1);
                if (idx < CAP2) { l2d[idx] = v.x; l2e[idx] = v.y; }
                else            acc = fmaf(v.y, v.x, acc);
            }
        }
        __syncthreads();

        // ---- exact O(k^2) rank resolution (crossing-entry semantics) ----
        const int   c2n  = s_int[1] < CAP2 ? s_int[1] : CAP2;
        const float Trem = T - mLo3;
        const float eThr = 1e-10f * Z;
        for (int i = tid; i < c2n; i += NTH) {
            float di = l2d[i], ei = l2e[i], rm = 0.f;
            for (int j = 0; j < c2n; j++) {
                float dj = l2d[j];
                rm += ((dj < di) || (dj == di && j < i)) ? l2e[j] : 0.f;
            }
            if (rm < Trem && ei > eThr) acc = fmaf(ei, di, acc);
        }

        // ---- fold row into per-thread accumulator (replaces block reduce) ----
        ctaAcc = fmaf(acc, rcpZ, ctaAcc);
        // ordering: next row's pass-1 + reduce-1 barriers precede all smem
        // rewrites (s_int reset in scan-1, list in compact, l2d in recompact).
    }

    // ---- one block reduce per CTA ----
#pragma unroll
    for (int o = 16; o; o >>= 1) ctaAcc += __shfl_xor_sync(0xffffffffu, ctaAcc, o);
    if (lane == 0) warpRed[wid] = ctaAcc;
    __syncthreads();
    if (tid == 0) {
        float tot = 0.f;
#pragma unroll
        for (int i = 0; i < 16; i++) tot += warpRed[i];
        atomicAdd(out, tot);
    }
}

extern "C" void kernel_launch(void* const* d_in, const int* in_sizes, int n_in,
                              void* d_out, int out_size)
{
    const float* x = (const float*)d_in[0];
    const float* y = (const float*)d_in[1];
    float* out = (float*)d_out;

    apml_zero_out<<<1, 1>>>(out);
    const int grid = (4 * MPTS) / RPC;   // 2048 CTAs
    apml_kernel<<<grid, NTH>>>(x, y, out);
}

// round 14
// speedup vs baseline: 2.4951x; 1.2648x over previous
#include <cuda_runtime.h>

// APMLSparse: x[B,N,3], y[B,M,3] fp32 -> scalar loss. B=4, N=M=4096.
// Per row: d_j = sqrt(max(||x-y_j||^2,1e-12)), e_j=exp(-d_j), Z=sum e_j.
// Kept = d-ascending prefix while exclusive cumulative mass < 0.8*Z (incl.
// crossing entry, p>1e-10 filter). loss += sum_kept e_j*d_j / Z.
//
// R10 = R4 (404us best) verbatim with ONE parameter change: stage-1 uses 32
// bins of width 0.5 (dynamic smem, 64KB) instead of 16 bins of width 1.
// Same loop shapes everywhere (the R6-R9 regressions all came from control-
// flow reshaping). Crossing bin ~28% of elements (was 55%), sub-bins width
// 1/64 -> compact band ~35 elems, penta + O(k^2) shrink 4x/16x.

#define NTH   512
#define NPT   8            // 4096 / NTH
#define RPC   8
#define MPTS  4096
#define NB    32           // bins per stage (width 0.5 stage 1, 1/64 stage 2)
#define HISTN (NB * NTH)   // 16384 floats = 64 KB (dynamic)
#define CAP   512
#define CAP2  128
#define HIST_BYTES (HISTN * 4)

__global__ void apml_zero_out(float* o) { o[0] = 0.0f; }

__global__ __launch_bounds__(NTH, 2)
void apml_kernel(const float* __restrict__ x, const float* __restrict__ y,
                 float* __restrict__ out)
{
    extern __shared__ float hist[];     // 64 KB private histogram columns
    __shared__ float2 list[CAP];        // 4 KB crossing-window elements
    __shared__ float  l2d[CAP2];        // final band
    __shared__ float  l2e[CAP2];
    __shared__ float  binTot[NB];
    __shared__ float  warpRed[64];
    __shared__ float  s_ctl[8];         // 0:Z 1:T 2:(c1|l2f) 3:h2f 4:mLo 5:l3 6:h3 7:mLo3
    __shared__ int    s_int[2];

    const int tid  = threadIdx.x, lane = tid & 31, wid = tid >> 5;
    const int cpb  = MPTS / RPC;                    // 512
    const int b    = blockIdx.x / cpb;
    const int rowBase = (blockIdx.x % cpb) * RPC;

    // 8 y-points per thread in registers, reused across RPC rows.
    float yx[NPT], yy[NPT], yz[NPT];
    const float* yb = y + (size_t)b * MPTS * 3;
#pragma unroll
    for (int k = 0; k < NPT; k++) {
        int j = k * NTH + tid;
        yx[k] = yb[j * 3 + 0];
        yy[k] = yb[j * 3 + 1];
        yz[k] = yb[j * 3 + 2];
    }

    float4* hist4 = (float4*)hist;
    float ctaAcc = 0.0f;

    for (int r = 0; r < RPC; r++) {
        const float* xp = x + ((size_t)b * MPTS + rowBase + r) * 3;
        const float x0 = __ldg(xp + 0);
        const float x1 = __ldg(xp + 1);
        const float x2 = __ldg(xp + 2);

        // ---- zero histogram (float4) ----
#pragma unroll
        for (int i = 0; i < HISTN / 4 / NTH; i++)
            hist4[tid + i * NTH] = make_float4(0.f, 0.f, 0.f, 0.f);
        if (tid == 0) { s_int[0] = 0; s_int[1] = 0; }
        __syncthreads();

        // ---- pass 1 fused with stage-1 fill: bins of width 0.5 over [0,16) ----
        float dreg[NPT];
#pragma unroll
        for (int k = 0; k < NPT; k++) {
            float dx = x0 - yx[k];
            float dy = x1 - yy[k];
            float dz = x2 - yz[k];
            float sq = fmaf(dx, dx, fmaf(dy, dy, dz * dz));
            sq = fmaxf(sq, 1e-12f);
            float d = sq * rsqrtf(sq);              // sqrt via MUFU.RSQ + FMUL
            dreg[k] = d;
            float e = __expf(-d);
            int bin = (int)(2.0f * d);              // exact 2^1 scaling
            bin = bin < (NB - 1) ? bin : (NB - 1);  // clamp stray large d
            hist[bin * NTH + tid] += e;             // conflict-free column
        }
        __syncthreads();

        // ---- stage-1 reduce: warp w sums bins 2w, 2w+1 via float4 ----
#pragma unroll
        for (int q = 0; q < 2; q++) {
            int bb = 2 * wid + q;
            float s = 0.f;
            int base = bb * (NTH / 4);
#pragma unroll
            for (int i = 0; i < NTH / 4 / 32; i++) {
                float4 v = hist4[base + lane + i * 32];
                s += (v.x + v.y) + (v.z + v.w);
            }
#pragma unroll
            for (int o = 16; o; o >>= 1) s += __shfl_xor_sync(0xffffffffu, s, o);
            if (lane == 0) binTot[bb] = s;
        }
        __syncthreads();

        // ---- stage-1 scan + pick (warp 0, 32 lanes = 32 bins) ----
        if (wid == 0) {
            float mm = binTot[lane];
            float incl = mm;
#pragma unroll
            for (int o = 1; o < 32; o <<= 1) {
                float t = __shfl_up_sync(0xffffffffu, incl, o);
                if (lane >= o) incl += t;
            }
            float total = __shfl_sync(0xffffffffu, incl, 31);
            float T = 0.8f * total;
            float excl = incl - mm;
            bool cross = (excl < T) && (incl >= T);
            unsigned bal = __ballot_sync(0xffffffffu, cross);
            int c1 = bal ? (__ffs(bal) - 1) : (NB - 1);
            float mlo = __shfl_sync(0xffffffffu, excl, c1);
            if (lane == 0) {
                s_ctl[0] = total;            // Z
                s_ctl[1] = T;
                s_ctl[2] = (float)c1;
                s_ctl[4] = mlo;              // mLo1
            }
        }
        __syncthreads();
        const float Z    = s_ctl[0];
        const float T    = s_ctl[1];
        const int   c1s  = ((int)s_ctl[2]) << 5;    // c1*32
        const float mLo1 = s_ctl[4];

        // ---- zero histogram for stage 2 ----
#pragma unroll
        for (int i = 0; i < HISTN / 4 / NTH; i++)
            hist4[tid + i * NTH] = make_float4(0.f, 0.f, 0.f, 0.f);
        __syncthreads();

        // ---- stage-2 fill: 32 sub-bins of width 1/64 over crossing bin ----
#pragma unroll
        for (int k = 0; k < NPT; k++) {
            float d = dreg[k];
            int b2 = (int)(d * 64.0f) - c1s;        // exact: 2^ scalings nest
            if ((unsigned)b2 < (unsigned)NB) {
                float e = __expf(-d);
                hist[b2 * NTH + tid] += e;
            }
        }
        __syncthreads();

        // ---- stage-2 reduce ----
#pragma unroll
        for (int q = 0; q < 2; q++) {
            int bb = 2 * wid + q;
            float s = 0.f;
            int base = bb * (NTH / 4);
#pragma unroll
            for (int i = 0; i < NTH / 4 / 32; i++) {
                float4 v = hist4[base + lane + i * 32];
                s += (v.x + v.y) + (v.z + v.w);
            }
#pragma unroll
            for (int o = 16; o; o >>= 1) s += __shfl_xor_sync(0xffffffffu, s, o);
            if (lane == 0) binTot[bb] = s;
        }
        __syncthreads();

        // ---- stage-2 scan + pick ----
        if (wid == 0) {
            float mm = binTot[lane];
            float incl = mm;
#pragma unroll
            for (int o = 1; o < 32; o <<= 1) {
                float t = __shfl_up_sync(0xffffffffu, incl, o);
                if (lane >= o) incl += t;
            }
            float excl = incl - mm;
            bool cross = (mLo1 + excl < T) && (mLo1 + incl >= T);
            unsigned bal = __ballot_sync(0xffffffffu, cross);
            int c2 = bal ? (__ffs(bal) - 1) : (NB - 1);   // fp-mismatch fallback
            float mlo2 = mLo1 + __shfl_sync(0xffffffffu, excl, c2);
            if (lane == 0) {
                float l2f = (float)(c1s + c2) * 0.015625f;  // exact fp (/64)
                s_ctl[2] = l2f;
                s_ctl[3] = l2f + 0.015625f;
                s_ctl[4] = mlo2;
            }
        }
        __syncthreads();
        const float l2f  = s_ctl[2];
        const float h2f  = s_ctl[3];
        const float mLo2 = s_ctl[4];

        // ---- compact crossing window + accumulate surely-kept sum ----
        float acc = 0.0f;
#pragma unroll
        for (int k = 0; k < NPT; k++) {
            float d = dreg[k];
            bool kept = d < l2f;
            bool band = (!kept) && (d < h2f);
            if (kept) acc = fmaf(__expf(-d), d, acc);
            unsigned mk = __ballot_sync(0xffffffffu, band);
            if (mk) {
                int leader = __ffs(mk) - 1;
                int base2 = 0;
                if (lane == leader) base2 = atomicAdd(&s_int[0], __popc(mk));
                base2 = __shfl_sync(0xffffffffu, base2, leader);
                if (band) {
                    int idx = base2 + __popc(mk & ((1u << lane) - 1u));
                    float e = __expf(-d);
                    if (idx < CAP) list[idx] = make_float2(d, e);
                    else           acc = fmaf(e, d, acc);  // overflow fallback
                }
            }
        }
        __syncthreads();
        const int cnt = s_int[0] < CAP ? s_int[0] : CAP;

        // ---- one penta round on the ~35-element list ----
        {
            float w  = (h2f - l2f) * 0.2f;
            float u1 = l2f + w, u2 = l2f + 2.f * w, u3 = l2f + 3.f * w, u4 = l2f + 4.f * w;
            float p0 = 0.f, p1 = 0.f, p2 = 0.f, p3 = 0.f;
            for (int i = tid; i < cnt; i += NTH) {
                float2 v = list[i];
                p0 += (v.x < u1) ? v.y : 0.f;
                p1 += (v.x < u2) ? v.y : 0.f;
                p2 += (v.x < u3) ? v.y : 0.f;
                p3 += (v.x < u4) ? v.y : 0.f;
            }
#pragma unroll
            for (int o = 16; o; o >>= 1) {
                p0 += __shfl_xor_sync(0xffffffffu, p0, o);
                p1 += __shfl_xor_sync(0xffffffffu, p1, o);
                p2 += __shfl_xor_sync(0xffffffffu, p2, o);
                p3 += __shfl_xor_sync(0xffffffffu, p3, o);
            }
            if (lane == 0) {
                warpRed[wid] = p0; warpRed[16 + wid] = p1;
                warpRed[32 + wid] = p2; warpRed[48 + wid] = p3;
            }
            __syncthreads();
            if (wid == 0) {
                float s = 0.f;
                if (lane < 4) {
#pragma unroll
                    for (int i = 0; i < 16; i++) s += warpRed[lane * 16 + i];
                }
                float m1 = __shfl_sync(0xffffffffu, s, 0);
                float m2 = __shfl_sync(0xffffffffu, s, 1);
                float m3 = __shfl_sync(0xffffffffu, s, 2);
                float m4 = __shfl_sync(0xffffffffu, s, 3);
                if (lane == 0) {
                    float l = l2f, h = u1, ml = mLo2;
                    if (mLo2 + m1 < T) { l = u1; h = u2; ml = mLo2 + m1;
                      if (mLo2 + m2 < T) { l = u2; h = u3; ml = mLo2 + m2;
                        if (mLo2 + m3 < T) { l = u3; h = u4; ml = mLo2 + m3;
                          if (mLo2 + m4 < T) { l = u4; h = h2f; ml = mLo2 + m4; } } } }
                    s_ctl[5] = l; s_ctl[6] = h; s_ctl[7] = ml;
                }
            }
            __syncthreads();
        }
        const float l3 = s_ctl[5], h3 = s_ctl[6], mLo3 = s_ctl[7];

        // ---- recompact final band ----
        for (int i = tid; i < cnt; i += NTH) {
            float2 v = list[i];
            if (v.x < l3) {
                acc = fmaf(v.y, v.x, acc);
            } else if (v.x < h3) {
                int idx = atomicAdd(&s_int[1], 1);
                if (idx < CAP2) { l2d[idx] = v.x; l2e[idx] = v.y; }
                else            acc = fmaf(v.y, v.x, acc);
            }
        }
        __syncthreads();

        // ---- exact O(k^2) rank resolution (crossing-entry semantics) ----
        const int   c2n  = s_int[1] < CAP2 ? s_int[1] : CAP2;
        const float Trem = T - mLo3;
        const float eThr = 1e-10f * Z;
        for (int i = tid; i < c2n; i += NTH) {
            float di = l2d[i], ei = l2e[i], rm = 0.f;
            for (int j = 0; j < c2n; j++) {
                float dj = l2d[j];
                rm += ((dj < di) || (dj == di && j < i)) ? l2e[j] : 0.f;
            }
            if (rm < Trem && ei > eThr) acc = fmaf(ei, di, acc);
        }

        // ---- row reduce ----
#pragma unroll
        for (int o = 16; o; o >>= 1) acc += __shfl_xor_sync(0xffffffffu, acc, o);
        if (lane == 0) warpRed[wid] = acc;
        __syncthreads();
        if (tid == 0) {
            float tot = 0.f;
#pragma unroll
            for (int i = 0; i < 16; i++) tot += warpRed[i];
            ctaAcc += tot / Z;
        }
        __syncthreads();   // protect smem before next row's zeroing
    }

    if (tid == 0) atomicAdd(out, ctaAcc);
}

extern "C" void kernel_launch(void* const* d_in, const int* in_sizes, int n_in,
                              void* d_out, int out_size)
{
    const float* x = (const float*)d_in[0];
    const float* y = (const float*)d_in[1];
    float* out = (float*)d_out;

    cudaFuncSetAttribute(apml_kernel,
                         cudaFuncAttributeMaxDynamicSharedMemorySize, HIST_BYTES);

    apml_zero_out<<<1, 1>>>(out);
    const int grid = (4 * MPTS) / RPC;   // 2048 CTAs
    apml_kernel<<<grid, NTH, HIST_BYTES>>>(x, y, out);
}